// round 4
// baseline (speedup 1.0000x reference)
#include <cuda_runtime.h>
#include <cuda_bf16.h>

// binary_conv: out = conv2d(x, sign(w)), SAME, stride 1, NHWC
// x: [32,112,112,128] f32   w: [3,3,128,256] f32   out: [32,112,112,256] f32
//
// Implicit GEMM: M = 32*112*112 = 401408, N = 256, K = 9*128 = 1152.
// Tile: BM=128, BN=64, BK=32, 256 threads, 8x4 accumulators per thread.

#define N_  32
#define H_  112
#define W_  112
#define C_  128
#define CO_ 256

#define BM 128
#define BN 64
#define BK 32

__global__ __launch_bounds__(256)
void bconv_kernel(const float* __restrict__ x,
                  const float* __restrict__ w,
                  float* __restrict__ out)
{
    __shared__ float As[BK][BM];      // K-major A tile (im2col rows)
    __shared__ float Bs[BK][BN];      // binarized weights
    __shared__ int   sH[BM], sW[BM], sB[BM];   // per-row coords

    const int tid = threadIdx.x;
    const int m0  = blockIdx.y * BM;   // spatial block
    const int n0  = blockIdx.x * BN;   // cout block (x-fastest -> A tile L2 reuse)

    // Precompute (n, h, w) for the 128 output rows of this block.
    if (tid < BM) {
        int m   = m0 + tid;
        int b   = m / (H_ * W_);
        int rem = m - b * (H_ * W_);
        sB[tid] = b;
        sH[tid] = rem / W_;
        sW[tid] = rem - (rem / W_) * W_;
    }
    __syncthreads();

    float acc[8][4];
#pragma unroll
    for (int i = 0; i < 8; ++i)
#pragma unroll
        for (int j = 0; j < 4; ++j) acc[i][j] = 0.f;

    const int tmg = tid & 15;    // m-group: rows tmg*8 .. tmg*8+7
    const int tng = tid >> 4;    // n-group: cols tng*4 .. tng*4+3

    // A loader: 128 rows x 32 cols; 2 threads per row, 16 floats each.
    const int ar  = tid >> 1;
    const int acg = (tid & 1) * 16;
    // B loader: 32 rows x 64 cols; 8 threads per row, 8 floats each.
    const int br  = tid >> 3;
    const int bcg = (tid & 7) * 8;

    const int aB = sB[ar];
    const int aH = sH[ar];
    const int aW = sW[ar];

    for (int pos = 0; pos < 9; ++pos) {
        const int kh = pos / 3;
        const int kw = pos - kh * 3;
        const int hin = aH + kh - 1;
        const int win = aW + kw - 1;
        const bool valid = (hin >= 0) && (hin < H_) && (win >= 0) && (win < W_);
        const float* asrc = x + (((size_t)(aB * H_ + hin) * W_ + win) * C_);
        const float* bsrc = w + ((size_t)pos * C_) * CO_ + n0;

        for (int cc = 0; cc < 4; ++cc) {           // 4 chunks of 32 channels
            // ---- global loads (before barrier: overlap latency) ----
            float av[16];
            if (valid) {
                const float4* p = (const float4*)(asrc + cc * 32 + acg);
#pragma unroll
                for (int q = 0; q < 4; ++q) {
                    float4 v = p[q];
                    av[q * 4 + 0] = v.x; av[q * 4 + 1] = v.y;
                    av[q * 4 + 2] = v.z; av[q * 4 + 3] = v.w;
                }
            } else {
#pragma unroll
                for (int q = 0; q < 16; ++q) av[q] = 0.f;
            }

            const float4* bp = (const float4*)(bsrc + (size_t)(cc * 32 + br) * CO_ + bcg);
            float4 b0 = bp[0];
            float4 b1 = bp[1];
            // binarize to sign(w): {-1, 0, +1}
            b0.x = (b0.x > 0.f) ? 1.f : ((b0.x < 0.f) ? -1.f : 0.f);
            b0.y = (b0.y > 0.f) ? 1.f : ((b0.y < 0.f) ? -1.f : 0.f);
            b0.z = (b0.z > 0.f) ? 1.f : ((b0.z < 0.f) ? -1.f : 0.f);
            b0.w = (b0.w > 0.f) ? 1.f : ((b0.w < 0.f) ? -1.f : 0.f);
            b1.x = (b1.x > 0.f) ? 1.f : ((b1.x < 0.f) ? -1.f : 0.f);
            b1.y = (b1.y > 0.f) ? 1.f : ((b1.y < 0.f) ? -1.f : 0.f);
            b1.z = (b1.z > 0.f) ? 1.f : ((b1.z < 0.f) ? -1.f : 0.f);
            b1.w = (b1.w > 0.f) ? 1.f : ((b1.w < 0.f) ? -1.f : 0.f);

            __syncthreads();   // previous compute done reading smem

            // ---- store tiles ----
#pragma unroll
            for (int q = 0; q < 16; ++q) As[acg + q][ar] = av[q];
            *(float4*)&Bs[br][bcg]     = b0;
            *(float4*)&Bs[br][bcg + 4] = b1;

            __syncthreads();

            // ---- compute: 32 k-steps, 8x4 FMA each ----
#pragma unroll
            for (int k = 0; k < BK; ++k) {
                float4 a0 = *(const float4*)&As[k][tmg * 8];
                float4 a1 = *(const float4*)&As[k][tmg * 8 + 4];
                float4 bb = *(const float4*)&Bs[k][tng * 4];
                float a[8] = {a0.x, a0.y, a0.z, a0.w, a1.x, a1.y, a1.z, a1.w};
                float b[4] = {bb.x, bb.y, bb.z, bb.w};
#pragma unroll
                for (int i = 0; i < 8; ++i)
#pragma unroll
                    for (int j = 0; j < 4; ++j)
                        acc[i][j] = fmaf(a[i], b[j], acc[i][j]);
            }
        }
    }

    // ---- writeback: 8 rows x float4 ----
#pragma unroll
    for (int i = 0; i < 8; ++i) {
        int m = m0 + tmg * 8 + i;
        float4 v = make_float4(acc[i][0], acc[i][1], acc[i][2], acc[i][3]);
        *(float4*)(out + (size_t)m * CO_ + n0 + tng * 4) = v;
    }
}

extern "C" void kernel_launch(void* const* d_in, const int* in_sizes, int n_in,
                              void* d_out, int out_size)
{
    (void)in_sizes; (void)n_in; (void)out_size;
    const float* x = (const float*)d_in[0];
    const float* w = (const float*)d_in[1];
    float* out = (float*)d_out;

    const int M = N_ * H_ * W_;          // 401408
    dim3 grid(CO_ / BN, M / BM);         // (4, 3136) — x fastest: cout blocks share A tile in L2
    bconv_kernel<<<grid, 256>>>(x, w, out);
}

// round 6
// speedup vs baseline: 5.7744x; 5.7744x over previous
#include <cuda_runtime.h>
#include <cuda_bf16.h>
#include <cstdint>

// binary_conv via mma.sync m16n8k16 bf16, split hi/lo (exact to ~2^-17).
// x: [32,112,112,128] f32  w: [3,3,128,256] f32 -> sign(w)  out: [32,112,112,256] f32
// GEMM: M=401408, N=256, K=1152. CTA tile 128x128, warp tile 32x64, BK=32, 2-stage cp.async.

#define N_  32
#define H_  112
#define W_  112
#define C_  128
#define CO_ 256
#define BM  128
#define BN  128
#define NCHUNK 36            // 9 taps * 4 chunks of 32 channels

#define NPIX (N_ * H_ * W_ * C_)      // 51380224

// Scratch (device globals; allocation APIs are banned)
__device__ __align__(16) __nv_bfloat16 g_xh[NPIX];        // hi plane
__device__ __align__(16) __nv_bfloat16 g_xl[NPIX];        // lo plane
__device__ __align__(16) __nv_bfloat16 g_wb[9 * 128 * 256]; // sign(w) bf16, [pos][c][co]

// smem layout per stage (bytes): A_hi 128x(40elem stride)=10240, A_lo 10240, B 32x(136)=8704
#define A_STRIDE_B 80
#define B_STRIDE_B 272
#define OFF_AH 0
#define OFF_AL 10240
#define OFF_B  20480
#define STAGE_BYTES 29184
#define SMEM_BYTES (2 * STAGE_BYTES)

// ---------------- PTX helpers (all legal on plain sm_103 target) ----------------
__device__ __forceinline__ uint32_t smem_u32(const void* p) {
    uint32_t a;
    asm("{ .reg .u64 t; cvta.to.shared.u64 t, %1; cvt.u32.u64 %0, t; }" : "=r"(a) : "l"(p));
    return a;
}
__device__ __forceinline__ void cp16(uint32_t dst, const void* src, uint32_t srcsz) {
    asm volatile("cp.async.cg.shared.global [%0], [%1], 16, %2;"
                 :: "r"(dst), "l"(src), "r"(srcsz));
}
__device__ __forceinline__ void cp_commit() {
    asm volatile("cp.async.commit_group;" ::: "memory");
}
template <int N>
__device__ __forceinline__ void cp_wait() {
    asm volatile("cp.async.wait_group %0;" :: "n"(N) : "memory");
}
__device__ __forceinline__ void ldsm4(uint32_t* r, uint32_t addr) {
    asm volatile("ldmatrix.sync.aligned.m8n8.x4.shared.b16 {%0,%1,%2,%3}, [%4];"
                 : "=r"(r[0]), "=r"(r[1]), "=r"(r[2]), "=r"(r[3]) : "r"(addr));
}
__device__ __forceinline__ void ldsm4t(uint32_t* r, uint32_t addr) {
    asm volatile("ldmatrix.sync.aligned.m8n8.x4.trans.shared.b16 {%0,%1,%2,%3}, [%4];"
                 : "=r"(r[0]), "=r"(r[1]), "=r"(r[2]), "=r"(r[3]) : "r"(addr));
}
__device__ __forceinline__ void mma16816(float* d, const uint32_t* a, uint32_t b0, uint32_t b1) {
    asm volatile(
        "mma.sync.aligned.m16n8k16.row.col.f32.bf16.bf16.f32 "
        "{%0,%1,%2,%3}, {%4,%5,%6,%7}, {%8,%9}, {%0,%1,%2,%3};"
        : "+f"(d[0]), "+f"(d[1]), "+f"(d[2]), "+f"(d[3])
        : "r"(a[0]), "r"(a[1]), "r"(a[2]), "r"(a[3]), "r"(b0), "r"(b1));
}

// ---------------- prepack kernels ----------------
__global__ void pack_x_kernel(const float* __restrict__ x) {
    int i4 = blockIdx.x * 256 + threadIdx.x;   // 12845056 threads, 4 elems each
    if (i4 >= NPIX / 4) return;
    float4 v = ((const float4*)x)[i4];
    __nv_bfloat16 h0 = __float2bfloat16(v.x), h1 = __float2bfloat16(v.y);
    __nv_bfloat16 h2 = __float2bfloat16(v.z), h3 = __float2bfloat16(v.w);
    __nv_bfloat16 l0 = __float2bfloat16(v.x - __bfloat162float(h0));
    __nv_bfloat16 l1 = __float2bfloat16(v.y - __bfloat162float(h1));
    __nv_bfloat16 l2 = __float2bfloat16(v.z - __bfloat162float(h2));
    __nv_bfloat16 l3 = __float2bfloat16(v.w - __bfloat162float(h3));
    uint16_t uh0 = *(uint16_t*)&h0, uh1 = *(uint16_t*)&h1, uh2 = *(uint16_t*)&h2, uh3 = *(uint16_t*)&h3;
    uint16_t ul0 = *(uint16_t*)&l0, ul1 = *(uint16_t*)&l1, ul2 = *(uint16_t*)&l2, ul3 = *(uint16_t*)&l3;
    ((uint2*)g_xh)[i4] = make_uint2((uint32_t)uh0 | ((uint32_t)uh1 << 16),
                                    (uint32_t)uh2 | ((uint32_t)uh3 << 16));
    ((uint2*)g_xl)[i4] = make_uint2((uint32_t)ul0 | ((uint32_t)ul1 << 16),
                                    (uint32_t)ul2 | ((uint32_t)ul3 << 16));
}

__global__ void pack_w_kernel(const float* __restrict__ w) {
    int idx = blockIdx.x * 256 + threadIdx.x;  // 9*128*256 = 294912
    if (idx >= 9 * 128 * 256) return;
    float v = w[idx];                          // [pos][c][co] contiguous == w layout
    float s = (v > 0.f) ? 1.f : ((v < 0.f) ? -1.f : 0.f);
    g_wb[idx] = __float2bfloat16(s);
}

// ---------------- main kernel ----------------
__global__ __launch_bounds__(256, 2)
void bconv_mma_kernel(float* __restrict__ out)
{
    extern __shared__ unsigned char smem[];
    const uint32_t sb = smem_u32(smem);
    const int tid = threadIdx.x;
    const int lane = tid & 31;
    const int wid = tid >> 5;
    const int wm = wid & 3;          // 0..3 : rows wm*32
    const int wn = wid >> 2;         // 0..1 : cols wn*64
    const int m0 = blockIdx.y * BM;
    const int n0 = blockIdx.x * BN;

    // A loader coords: 2 threads per row, 16 channels each half
    const int lr_row = tid >> 1;
    const int lhalf  = tid & 1;
    const int m  = m0 + lr_row;
    const int b  = m / (H_ * W_);
    const int rm = m - b * (H_ * W_);
    const int hh = rm / W_;
    const int ww = rm - hh * W_;
    // B loader coords
    const int bkr  = tid >> 3;        // 0..31 k-row
    const int bseg = (tid & 7) * 2;   // 16B segment pair

    float acc[2][8][4];
#pragma unroll
    for (int a = 0; a < 2; ++a)
#pragma unroll
        for (int j = 0; j < 8; ++j)
#pragma unroll
            for (int q = 0; q < 4; ++q) acc[a][j][q] = 0.f;

    // ---- pipelined chunk loader ----
    auto issue = [&](int s, int stage) {
        const int pos = s >> 2, cc = s & 3;
        const int kh = pos / 3, kw = pos - kh * 3;
        const uint32_t base = sb + (uint32_t)stage * STAGE_BYTES;
        // A (hi + lo): row lr_row, channels cc*32 + lhalf*16 .. +15
        {
            const int hin = hh + kh - 1, win = ww + kw - 1;
            const bool valid = (hin >= 0) && (hin < H_) && (win >= 0) && (win < W_);
            const uint32_t sz = valid ? 16u : 0u;
            const size_t p = (((size_t)(b * H_ + hin)) * W_ + win) * C_ + cc * 32 + lhalf * 16;
            const uint32_t dA = base + (uint32_t)lr_row * A_STRIDE_B + (uint32_t)lhalf * 32;
            cp16(dA + OFF_AH,      g_xh + p,     sz);
            cp16(dA + OFF_AH + 16, g_xh + p + 8, sz);
            cp16(dA + OFF_AL,      g_xl + p,     sz);
            cp16(dA + OFF_AL + 16, g_xl + p + 8, sz);
        }
        // B: 32 k-rows x 128 n (bf16), pre-binarized
        {
            const size_t rb = ((size_t)(pos * C_ + cc * 32 + bkr)) * CO_ + n0 + bseg * 8;
            const uint32_t dB = base + OFF_B + (uint32_t)bkr * B_STRIDE_B + (uint32_t)bseg * 16;
            cp16(dB,      g_wb + rb,     16u);
            cp16(dB + 16, g_wb + rb + 8, 16u);
        }
        cp_commit();
    };

    // ldmatrix lane addressing (shared by A and B patterns)
    const int lr8 = (lane & 7) + ((lane >> 3) & 1) * 8;
    const int lh8 = lane >> 4;

    issue(0, 0);

    for (int s = 0; s < NCHUNK; ++s) {
        const int stage = s & 1;
        if (s + 1 < NCHUNK) issue(s + 1, (s + 1) & 1);

        if (s + 1 < NCHUNK) cp_wait<1>(); else cp_wait<0>();
        __syncthreads();

        const uint32_t base = sb + (uint32_t)stage * STAGE_BYTES;
        const uint32_t Ah = base + OFF_AH + (uint32_t)(wm * 32) * A_STRIDE_B;
        const uint32_t Al = base + OFF_AL + (uint32_t)(wm * 32) * A_STRIDE_B;
        const uint32_t Bb = base + OFF_B + (uint32_t)(wn * 64) * 2;

#pragma unroll
        for (int ks = 0; ks < 2; ++ks) {
            uint32_t ah[2][4], al[2][4], bf[4][4];
#pragma unroll
            for (int mt = 0; mt < 2; ++mt) {
                const uint32_t ao = (uint32_t)(mt * 16 + lr8) * A_STRIDE_B + ks * 32 + lh8 * 16;
                ldsm4(ah[mt], Ah + ao);
                ldsm4(al[mt], Al + ao);
            }
#pragma unroll
            for (int jn = 0; jn < 4; ++jn) {
                const uint32_t bo = (uint32_t)(ks * 16 + lr8) * B_STRIDE_B + jn * 32 + lh8 * 16;
                ldsm4t(bf[jn], Bb + bo);
            }
#pragma unroll
            for (int mt = 0; mt < 2; ++mt)
#pragma unroll
                for (int j = 0; j < 8; ++j) {
                    const uint32_t b0 = bf[j >> 1][(j & 1) * 2];
                    const uint32_t b1 = bf[j >> 1][(j & 1) * 2 + 1];
                    mma16816(acc[mt][j], ah[mt], b0, b1);
                    mma16816(acc[mt][j], al[mt], b0, b1);
                }
        }
        __syncthreads();
    }

    // ---- epilogue: direct gmem stores ----
    const int qr = lane >> 2, qc = lane & 3;
#pragma unroll
    for (int mt = 0; mt < 2; ++mt) {
        const int mrow = m0 + wm * 32 + mt * 16 + qr;
        float* o0 = out + (size_t)mrow * CO_ + n0 + wn * 64;
        float* o1 = out + (size_t)(mrow + 8) * CO_ + n0 + wn * 64;
#pragma unroll
        for (int j = 0; j < 8; ++j) {
            *(float2*)(o0 + j * 8 + qc * 2) = make_float2(acc[mt][j][0], acc[mt][j][1]);
            *(float2*)(o1 + j * 8 + qc * 2) = make_float2(acc[mt][j][2], acc[mt][j][3]);
        }
    }
}

extern "C" void kernel_launch(void* const* d_in, const int* in_sizes, int n_in,
                              void* d_out, int out_size)
{
    (void)in_sizes; (void)n_in; (void)out_size;
    const float* x = (const float*)d_in[0];
    const float* w = (const float*)d_in[1];
    float* out = (float*)d_out;

    static int smem_set = 0;  // host-side attribute config (idempotent, no device state)
    cudaFuncSetAttribute(bconv_mma_kernel,
                         cudaFuncAttributeMaxDynamicSharedMemorySize, SMEM_BYTES);
    (void)smem_set;

    pack_x_kernel<<<(NPIX / 4 + 255) / 256, 256>>>(x);
    pack_w_kernel<<<(9 * 128 * 256 + 255) / 256, 256>>>(w);

    const int M = N_ * H_ * W_;                 // 401408
    dim3 grid(CO_ / BN, M / BM);                // (2, 3136)
    bconv_mma_kernel<<<grid, 256, SMEM_BYTES>>>(out);
}

// round 7
// speedup vs baseline: 9.8306x; 1.7024x over previous
#include <cuda_runtime.h>
#include <cuda_fp16.h>
#include <cstdint>

// binary_conv via mma.sync m16n8k16 fp16 single-pass (norm rel err ~3e-4 < 1e-3).
// x: [32,112,112,128] f32  w: [3,3,128,256] f32 -> sign(w)  out: [32,112,112,256] f32
// GEMM: M=401408, N=256, K=1152. CTA tile 128x128, warp tile 32x64, BK=32, 4-stage cp.async.

#define N_  32
#define H_  112
#define W_  112
#define C_  128
#define CO_ 256
#define BM  128
#define BN  128
#define NCHUNK 36            // 9 taps * 4 chunks of 32 channels

#define NPIX (N_ * H_ * W_ * C_)      // 51380224

// Scratch (device globals; allocation APIs are banned)
__device__ __align__(16) __half g_xp[NPIX];          // x in fp16
__device__ __align__(16) __half g_wb[9 * 128 * 256]; // sign(w) fp16, [pos][c][co]

// smem per stage: A 128 rows x 80B stride = 10240, B 32 rows x 272B = 8704
#define A_STRIDE_B 80
#define B_STRIDE_B 272
#define OFF_A 0
#define OFF_B 10240
#define STAGE_BYTES 18944
#define NSTAGES 4
#define SMEM_BYTES (NSTAGES * STAGE_BYTES)

// ---------------- PTX helpers (legal on plain sm_103 target) ----------------
__device__ __forceinline__ uint32_t smem_u32(const void* p) {
    uint32_t a;
    asm("{ .reg .u64 t; cvta.to.shared.u64 t, %1; cvt.u32.u64 %0, t; }" : "=r"(a) : "l"(p));
    return a;
}
__device__ __forceinline__ void cp16(uint32_t dst, const void* src, uint32_t srcsz) {
    asm volatile("cp.async.cg.shared.global [%0], [%1], 16, %2;"
                 :: "r"(dst), "l"(src), "r"(srcsz));
}
__device__ __forceinline__ void cp_commit() {
    asm volatile("cp.async.commit_group;" ::: "memory");
}
template <int N>
__device__ __forceinline__ void cp_wait() {
    asm volatile("cp.async.wait_group %0;" :: "n"(N) : "memory");
}
__device__ __forceinline__ void ldsm4(uint32_t* r, uint32_t addr) {
    asm volatile("ldmatrix.sync.aligned.m8n8.x4.shared.b16 {%0,%1,%2,%3}, [%4];"
                 : "=r"(r[0]), "=r"(r[1]), "=r"(r[2]), "=r"(r[3]) : "r"(addr));
}
__device__ __forceinline__ void ldsm4t(uint32_t* r, uint32_t addr) {
    asm volatile("ldmatrix.sync.aligned.m8n8.x4.trans.shared.b16 {%0,%1,%2,%3}, [%4];"
                 : "=r"(r[0]), "=r"(r[1]), "=r"(r[2]), "=r"(r[3]) : "r"(addr));
}
__device__ __forceinline__ void mma16816(float* d, const uint32_t* a, uint32_t b0, uint32_t b1) {
    asm volatile(
        "mma.sync.aligned.m16n8k16.row.col.f32.f16.f16.f32 "
        "{%0,%1,%2,%3}, {%4,%5,%6,%7}, {%8,%9}, {%0,%1,%2,%3};"
        : "+f"(d[0]), "+f"(d[1]), "+f"(d[2]), "+f"(d[3])
        : "r"(a[0]), "r"(a[1]), "r"(a[2]), "r"(a[3]), "r"(b0), "r"(b1));
}

// ---------------- prepack kernels ----------------
__global__ void pack_x_kernel(const float* __restrict__ x) {
    int i4 = blockIdx.x * 256 + threadIdx.x;   // 4 elems each
    if (i4 >= NPIX / 4) return;
    float4 v = ((const float4*)x)[i4];
    __half2 p0 = __floats2half2_rn(v.x, v.y);
    __half2 p1 = __floats2half2_rn(v.z, v.w);
    ((uint2*)g_xp)[i4] = make_uint2(*(uint32_t*)&p0, *(uint32_t*)&p1);
}

__global__ void pack_w_kernel(const float* __restrict__ w) {
    int idx = blockIdx.x * 256 + threadIdx.x;  // 9*128*256 = 294912
    if (idx >= 9 * 128 * 256) return;
    float v = w[idx];                          // [pos][c][co] contiguous
    float s = (v > 0.f) ? 1.f : ((v < 0.f) ? -1.f : 0.f);
    g_wb[idx] = __float2half(s);
}

// ---------------- main kernel ----------------
__global__ __launch_bounds__(256, 2)
void bconv_mma_kernel(float* __restrict__ out)
{
    extern __shared__ unsigned char smem[];
    const uint32_t sb = smem_u32(smem);
    const int tid = threadIdx.x;
    const int lane = tid & 31;
    const int wid = tid >> 5;
    const int wm = wid & 3;          // 0..3 : rows wm*32
    const int wn = wid >> 2;         // 0..1 : cols wn*64
    const int m0 = blockIdx.y * BM;
    const int n0 = blockIdx.x * BN;

    // A loader coords: 2 threads per row, 16 channels each half
    const int lr_row = tid >> 1;
    const int lhalf  = tid & 1;
    const int m  = m0 + lr_row;
    const int b  = m / (H_ * W_);
    const int rm = m - b * (H_ * W_);
    const int hh = rm / W_;
    const int ww = rm - hh * W_;
    // B loader coords
    const int bkr  = tid >> 3;        // 0..31 k-row
    const int bseg = (tid & 7) * 2;   // 16B segment pair

    float acc[2][8][4];
#pragma unroll
    for (int a = 0; a < 2; ++a)
#pragma unroll
        for (int j = 0; j < 8; ++j)
#pragma unroll
            for (int q = 0; q < 4; ++q) acc[a][j][q] = 0.f;

    // ---- chunk loader (ends with commit_group) ----
    auto issue = [&](int s, int stage) {
        const int pos = s >> 2, cc = s & 3;
        const int kh = pos / 3, kw = pos - kh * 3;
        const uint32_t base = sb + (uint32_t)stage * STAGE_BYTES;
        // A: row lr_row, channels cc*32 + lhalf*16 .. +15
        {
            const int hin = hh + kh - 1, win = ww + kw - 1;
            const bool valid = (hin >= 0) && (hin < H_) && (win >= 0) && (win < W_);
            const uint32_t sz = valid ? 16u : 0u;
            const size_t p = (((size_t)(b * H_ + hin)) * W_ + win) * C_ + cc * 32 + lhalf * 16;
            const uint32_t dA = base + OFF_A + (uint32_t)lr_row * A_STRIDE_B + (uint32_t)lhalf * 32;
            cp16(dA,      g_xp + p,     sz);
            cp16(dA + 16, g_xp + p + 8, sz);
        }
        // B: 32 k-rows x 128 n (fp16), pre-binarized
        {
            const size_t rb = ((size_t)(pos * C_ + cc * 32 + bkr)) * CO_ + n0 + bseg * 8;
            const uint32_t dB = base + OFF_B + (uint32_t)bkr * B_STRIDE_B + (uint32_t)bseg * 16;
            cp16(dB,      g_wb + rb,     16u);
            cp16(dB + 16, g_wb + rb + 8, 16u);
        }
        cp_commit();
    };

    // ldmatrix lane addressing
    const int lr8 = (lane & 7) + ((lane >> 3) & 1) * 8;
    const int lh8 = lane >> 4;

    issue(0, 0);
    issue(1, 1);
    issue(2, 2);

    for (int s = 0; s < NCHUNK; ++s) {
        const int stage = s & 3;
        if (s + 3 < NCHUNK) issue(s + 3, (s + 3) & 3);
        else cp_commit();                  // keep group count uniform

        cp_wait<3>();                      // stage s resident
        __syncthreads();

        const uint32_t base = sb + (uint32_t)stage * STAGE_BYTES;
        const uint32_t Aa = base + OFF_A + (uint32_t)(wm * 32) * A_STRIDE_B;
        const uint32_t Bb = base + OFF_B + (uint32_t)(wn * 64) * 2;

#pragma unroll
        for (int ks = 0; ks < 2; ++ks) {
            uint32_t af[2][4], bf[4][4];
#pragma unroll
            for (int mt = 0; mt < 2; ++mt) {
                const uint32_t ao = (uint32_t)(mt * 16 + lr8) * A_STRIDE_B + ks * 32 + lh8 * 16;
                ldsm4(af[mt], Aa + ao);
            }
#pragma unroll
            for (int jn = 0; jn < 4; ++jn) {
                const uint32_t bo = (uint32_t)(ks * 16 + lr8) * B_STRIDE_B + jn * 32 + lh8 * 16;
                ldsm4t(bf[jn], Bb + bo);
            }
#pragma unroll
            for (int mt = 0; mt < 2; ++mt)
#pragma unroll
                for (int j = 0; j < 8; ++j) {
                    const uint32_t b0 = bf[j >> 1][(j & 1) * 2];
                    const uint32_t b1 = bf[j >> 1][(j & 1) * 2 + 1];
                    mma16816(acc[mt][j], af[mt], b0, b1);
                }
        }
        __syncthreads();
    }

    // ---- epilogue: direct gmem stores ----
    const int qr = lane >> 2, qc = lane & 3;
#pragma unroll
    for (int mt = 0; mt < 2; ++mt) {
        const int mrow = m0 + wm * 32 + mt * 16 + qr;
        float* o0 = out + (size_t)mrow * CO_ + n0 + wn * 64;
        float* o1 = out + (size_t)(mrow + 8) * CO_ + n0 + wn * 64;
#pragma unroll
        for (int j = 0; j < 8; ++j) {
            *(float2*)(o0 + j * 8 + qc * 2) = make_float2(acc[mt][j][0], acc[mt][j][1]);
            *(float2*)(o1 + j * 8 + qc * 2) = make_float2(acc[mt][j][2], acc[mt][j][3]);
        }
    }
}

extern "C" void kernel_launch(void* const* d_in, const int* in_sizes, int n_in,
                              void* d_out, int out_size)
{
    (void)in_sizes; (void)n_in; (void)out_size;
    const float* x = (const float*)d_in[0];
    const float* w = (const float*)d_in[1];
    float* out = (float*)d_out;

    cudaFuncSetAttribute(bconv_mma_kernel,
                         cudaFuncAttributeMaxDynamicSharedMemorySize, SMEM_BYTES);

    pack_x_kernel<<<(NPIX / 4 + 255) / 256, 256>>>(x);
    pack_w_kernel<<<(9 * 128 * 256 + 255) / 256, 256>>>(w);

    const int M = N_ * H_ * W_;                 // 401408
    dim3 grid(CO_ / BN, M / BM);                // (2, 3136)
    bconv_mma_kernel<<<grid, 256, SMEM_BYTES>>>(out);
}